// round 1
// baseline (speedup 1.0000x reference)
#include <cuda_runtime.h>
#include <cuda_bf16.h>
#include <math.h>

// ---------------- problem constants ----------------
#define B    4
#define N    16384
#define CIN  4
#define SD   3
#define W    256
#define L    8
#define M    32
#define H    8
#define FF   1024
#define TF   4
#define DH   32          // W/H

#define TOK1 32          // tokens per block in slice kernel
#define TOK3 16          // tokens per block in ffn kernel
#define JC   128         // FF chunk in ffn kernel

// ---------------- device scratch (no allocation allowed) ----------------
__device__ float g_x[(size_t)B * N * W];        // 64 MB activations
__device__ float g_w[(size_t)B * N * M];        // 8 MB slice weights
__device__ float g_z[B * M * W];                // slice tokens (pre-norm)
__device__ float g_wsum[B * M];
__device__ float g_qkv[B * M * 3 * W];
__device__ float g_o[B * M * W];
__device__ float g_zp[B * M * W];

// ---------------- K0: time-embed + input concat + embed GEMM ----------------
__global__ void __launch_bounds__(256) embed_kernel(
    const float* __restrict__ feat, const float* __restrict__ coords,
    const float* __restrict__ tn, const float* __restrict__ ew,
    const float* __restrict__ eb)
{
    int token = blockIdx.x;          // 0 .. B*N-1
    int b = token / N;
    int c = threadIdx.x;
    __shared__ float f[16];
    if (threadIdx.x < CIN) {
        f[threadIdx.x] = feat[(size_t)token * CIN + threadIdx.x];
    } else if (threadIdx.x < CIN + SD) {
        f[threadIdx.x] = coords[(size_t)token * SD + (threadIdx.x - CIN)];
    } else if (threadIdx.x < CIN + SD + 2 * TF) {
        int k = threadIdx.x - (CIN + SD);      // 0..7
        int i = k & 3;
        float omega = powf(1000.0f, -(float)i / (float)TF);
        float ang = omega * (tn[b] * 1000.0f);
        f[threadIdx.x] = (k < TF) ? sinf(ang) : cosf(ang);
    }
    __syncthreads();
    float acc = eb[c];
#pragma unroll
    for (int k = 0; k < CIN + SD + 2 * TF; k++) acc += f[k] * ew[k * W + c];
    g_x[(size_t)token * W + c] = acc;
}

// ---------------- zero z / wsum each layer ----------------
__global__ void zero_zw_kernel()
{
    int i = blockIdx.x * 256 + threadIdx.x;
    if (i < B * M * W) g_z[i] = 0.0f;
    if (i < B * M)     g_wsum[i] = 0.0f;
}

// ---------------- K1: LN1 + slice logits + softmax + z/wsum accumulation ----
__global__ void __launch_bounds__(256) slice_kernel(
    const float* __restrict__ ln_g, const float* __restrict__ ln_b,
    const float* __restrict__ sw, const float* __restrict__ sb, int layer)
{
    __shared__ float hs[TOK1][W];       // 32 KB   LN output
    __shared__ float ws[TOK1][M];       // 4 KB    slice weights
    __shared__ float inv[TOK1];

    int nb = N / TOK1;
    int b = blockIdx.x / nb;
    int t0 = (blockIdx.x % nb) * TOK1;
    int tid = threadIdx.x;
    int warp = tid >> 5, lane = tid & 31;

    const float* g  = ln_g + layer * W;
    const float* be = ln_b + layer * W;

    // LayerNorm: 8 warps, 4 tokens each
    for (int t = warp; t < TOK1; t += 8) {
        const float* xr = g_x + ((size_t)(b * N + t0 + t)) * W;
        float v[8]; float s = 0.f, s2 = 0.f;
#pragma unroll
        for (int i = 0; i < 8; i++) { v[i] = xr[lane + 32 * i]; s += v[i]; s2 += v[i] * v[i]; }
#pragma unroll
        for (int o = 16; o > 0; o >>= 1) {
            s  += __shfl_xor_sync(0xffffffffu, s,  o);
            s2 += __shfl_xor_sync(0xffffffffu, s2, o);
        }
        float mean = s * (1.0f / W);
        float var  = s2 * (1.0f / W) - mean * mean;
        float r = rsqrtf(var + 1e-5f);
#pragma unroll
        for (int i = 0; i < 8; i++) {
            int c = lane + 32 * i;
            hs[t][c] = (v[i] - mean) * r * g[c] + be[c];
        }
    }
    __syncthreads();

    // slice logits: 32 tok x 32 m, 4 per thread
    const float* swl = sw + (size_t)layer * W * M;
    float lg[4];
#pragma unroll
    for (int r = 0; r < 4; r++) {
        int idx = tid + 256 * r;
        int t = idx / M, m = idx % M;
        float acc = sb[layer * M + m];
#pragma unroll 8
        for (int c = 0; c < W; c++) acc += hs[t][c] * swl[c * M + m];
        lg[r] = acc;
    }
#pragma unroll
    for (int r = 0; r < 4; r++) {
        int idx = tid + 256 * r;
        ws[idx / M][idx % M] = lg[r];
    }
    __syncthreads();

    // softmax over M per token
    if (tid < TOK1) {
        int t = tid;
        float mx = -1e30f;
#pragma unroll
        for (int m = 0; m < M; m++) mx = fmaxf(mx, ws[t][m]);
        float sum = 0.f;
#pragma unroll
        for (int m = 0; m < M; m++) { float e = expf(ws[t][m] - mx); ws[t][m] = e; sum += e; }
        inv[t] = 1.0f / sum;
    }
    __syncthreads();

    // normalize + write w to global
#pragma unroll
    for (int r = 0; r < 4; r++) {
        int idx = tid + 256 * r;
        int t = idx / M, m = idx % M;
        float v = ws[t][m] * inv[t];
        ws[t][m] = v;
        g_w[((size_t)(b * N + t0 + t)) * M + m] = v;
    }
    __syncthreads();

    // wsum partials
    if (tid < M) {
        float s = 0.f;
#pragma unroll
        for (int t = 0; t < TOK1; t++) s += ws[t][tid];
        atomicAdd(&g_wsum[b * M + tid], s);
    }

    // z accumulation: thread owns channel c = tid
    int c = tid;
    float zacc[M];
#pragma unroll
    for (int m = 0; m < M; m++) zacc[m] = 0.f;
    for (int t = 0; t < TOK1; t++) {
        float hv = hs[t][c];
#pragma unroll
        for (int m = 0; m < M; m++) zacc[m] += ws[t][m] * hv;
    }
#pragma unroll
    for (int m = 0; m < M; m++) atomicAdd(&g_z[(b * M + m) * W + c], zacc[m]);
}

// ---------------- K2a: z/wsum -> qkv ----------------
__global__ void __launch_bounds__(256) qkv_kernel(
    const float* __restrict__ qkvw, const float* __restrict__ qkvb, int layer)
{
    int b = blockIdx.x / M, m = blockIdx.x % M;
    __shared__ float zs[W];
    float wsv = fmaxf(g_wsum[b * M + m], 1e-8f);
    zs[threadIdx.x] = g_z[(b * M + m) * W + threadIdx.x] / wsv;
    __syncthreads();
    const float* wq = qkvw + (size_t)layer * W * 3 * W;
#pragma unroll
    for (int r = 0; r < 3; r++) {
        int j = threadIdx.x + 256 * r;
        float acc = qkvb[layer * 3 * W + j];
#pragma unroll 8
        for (int c = 0; c < W; c++) acc += zs[c] * wq[(size_t)c * (3 * W) + j];
        g_qkv[(size_t)(b * M + m) * (3 * W) + j] = acc;
    }
}

// ---------------- K2b: 32x32 latent attention per (b,h) ----------------
__global__ void __launch_bounds__(256) attn_kernel()
{
    int b = blockIdx.x / H, h = blockIdx.x % H;
    __shared__ float q[M][DH], k[M][DH], v[M][DH], a[M][M];
    int tid = threadIdx.x;
    for (int i = tid; i < M * DH; i += 256) {
        int m = i / DH, d = i % DH;
        const float* base = g_qkv + (size_t)(b * M + m) * (3 * W);
        q[m][d] = base[h * DH + d];
        k[m][d] = base[W + h * DH + d];
        v[m][d] = base[2 * W + h * DH + d];
    }
    __syncthreads();
    const float scale = 0.17677669529663687f;   // 1/sqrt(32)
    for (int i = tid; i < M * M; i += 256) {
        int m = i / M, n2 = i % M;
        float acc = 0.f;
#pragma unroll
        for (int d = 0; d < DH; d++) acc += q[m][d] * k[n2][d];
        a[m][n2] = acc * scale;
    }
    __syncthreads();
    if (tid < M) {
        float mx = -1e30f;
#pragma unroll
        for (int n2 = 0; n2 < M; n2++) mx = fmaxf(mx, a[tid][n2]);
        float s = 0.f;
#pragma unroll
        for (int n2 = 0; n2 < M; n2++) { float e = expf(a[tid][n2] - mx); a[tid][n2] = e; s += e; }
        float is = 1.0f / s;
#pragma unroll
        for (int n2 = 0; n2 < M; n2++) a[tid][n2] *= is;
    }
    __syncthreads();
    for (int i = tid; i < M * DH; i += 256) {
        int m = i / DH, d = i % DH;
        float acc = 0.f;
#pragma unroll
        for (int n2 = 0; n2 < M; n2++) acc += a[m][n2] * v[n2][d];
        g_o[(size_t)(b * M + m) * W + h * DH + d] = acc;
    }
}

// ---------------- K2c: zp = o @ out_w + out_b ----------------
__global__ void __launch_bounds__(256) zp_kernel(
    const float* __restrict__ ow, const float* __restrict__ ob, int layer)
{
    int b = blockIdx.x / M, m = blockIdx.x % M;
    __shared__ float os[W];
    os[threadIdx.x] = g_o[(size_t)(b * M + m) * W + threadIdx.x];
    __syncthreads();
    const float* wl = ow + (size_t)layer * W * W;
    int c = threadIdx.x;
    float acc = ob[layer * W + c];
#pragma unroll 8
    for (int k2 = 0; k2 < W; k2++) acc += os[k2] * wl[(size_t)k2 * W + c];
    g_zp[(size_t)(b * M + m) * W + c] = acc;
}

// ---------------- K3: broadcast-back + residual + LN2 + FFN + residual -----
__global__ void __launch_bounds__(256) ffn_kernel(
    const float* __restrict__ ln2g, const float* __restrict__ ln2b,
    const float* __restrict__ f1w, const float* __restrict__ f1b,
    const float* __restrict__ f2w, const float* __restrict__ f2b, int layer)
{
    __shared__ float xh[TOK3][W];    // 16 KB  x_mid then h2 (in-place)
    __shared__ float ts[TOK3][JC];   // 8 KB   gelu(ffn1) chunk
    __shared__ float wt[TOK3][M];    // 2 KB   slice weights tile

    int nb = N / TOK3;
    int b = blockIdx.x / nb;
    int t0 = (blockIdx.x % nb) * TOK3;
    int tid = threadIdx.x;

    // zp column (this thread's channel) in registers
    float zpc[M];
#pragma unroll
    for (int m = 0; m < M; m++) zpc[m] = g_zp[(size_t)(b * M + m) * W + tid];

    for (int i = tid; i < TOK3 * M; i += 256)
        wt[i / M][i % M] = g_w[((size_t)(b * N) + t0 + i / M) * M + (i % M)];
    __syncthreads();

    // x_mid = x + w @ zp ; outacc starts the second residual (+ffn2_b)
    const float* f2bl = f2b + layer * W;
    float outacc[TOK3];
    float bias2 = f2bl[tid];
#pragma unroll
    for (int t = 0; t < TOK3; t++) {
        float acc = g_x[((size_t)(b * N) + t0 + t) * W + tid];
#pragma unroll
        for (int m = 0; m < M; m++) acc += wt[t][m] * zpc[m];
        xh[t][tid] = acc;
        outacc[t] = acc + bias2;
    }
    __syncthreads();

    // LayerNorm2 in place: 8 warps x 2 tokens
    int warp = tid >> 5, lane = tid & 31;
    const float* g2 = ln2g + layer * W;
    const float* b2 = ln2b + layer * W;
    for (int t = warp; t < TOK3; t += 8) {
        float v[8]; float s = 0.f, s2 = 0.f;
#pragma unroll
        for (int i = 0; i < 8; i++) { v[i] = xh[t][lane + 32 * i]; s += v[i]; s2 += v[i] * v[i]; }
#pragma unroll
        for (int o = 16; o > 0; o >>= 1) {
            s  += __shfl_xor_sync(0xffffffffu, s,  o);
            s2 += __shfl_xor_sync(0xffffffffu, s2, o);
        }
        float mean = s * (1.0f / W);
        float var  = s2 * (1.0f / W) - mean * mean;
        float r = rsqrtf(var + 1e-5f);
#pragma unroll
        for (int i = 0; i < 8; i++) {
            int c = lane + 32 * i;
            xh[t][c] = (v[i] - mean) * r * g2[c] + b2[c];
        }
    }
    __syncthreads();

    const float* w1 = f1w + (size_t)layer * W * FF;
    const float* w2 = f2w + (size_t)layer * FF * W;
    const float* b1 = f1b + layer * FF;
    int jloc = tid & (JC - 1);
    int tg   = tid >> 7;     // token group 0/1 (8 tokens each)

    for (int jc = 0; jc < FF; jc += JC) {
        int j = jc + jloc;
        float acc8[8];
        float bj = b1[j];
#pragma unroll
        for (int i = 0; i < 8; i++) acc8[i] = bj;
        for (int c = 0; c < W; c++) {
            float wv = w1[(size_t)c * FF + j];
#pragma unroll
            for (int i = 0; i < 8; i++) acc8[i] += xh[tg * 8 + i][c] * wv;
        }
#pragma unroll
        for (int i = 0; i < 8; i++) {
            float xg = acc8[i];
            ts[tg * 8 + i][jloc] = 0.5f * xg * (1.0f + erff(xg * 0.7071067811865476f));
        }
        __syncthreads();
        for (int jj = 0; jj < JC; jj++) {
            float wv = w2[(size_t)(jc + jj) * W + tid];
#pragma unroll
            for (int t = 0; t < TOK3; t++) outacc[t] += ts[t][jj] * wv;
        }
        __syncthreads();
    }

#pragma unroll
    for (int t = 0; t < TOK3; t++)
        g_x[((size_t)(b * N) + t0 + t) * W + tid] = outacc[t];
}

// ---------------- K5: final projection ----------------
__global__ void __launch_bounds__(256) proj_kernel(
    const float* __restrict__ pw, const float* __restrict__ pb,
    float* __restrict__ out)
{
    __shared__ float xs[16][W];
    size_t t0 = (size_t)blockIdx.x * 16;
    for (int i = threadIdx.x; i < 16 * W; i += 256)
        xs[i >> 8][i & 255] = g_x[t0 * W + i];
    __syncthreads();
    if (threadIdx.x < 64) {
        int t = threadIdx.x >> 2, o = threadIdx.x & 3;
        float acc = pb[o];
#pragma unroll 8
        for (int c = 0; c < W; c++) acc += xs[t][c] * pw[c * CIN + o];
        out[(t0 + t) * CIN + o] = acc;
    }
}

// ---------------- launch ----------------
extern "C" void kernel_launch(void* const* d_in, const int* in_sizes, int n_in,
                              void* d_out, int out_size)
{
    const float* feat   = (const float*)d_in[0];
    const float* coords = (const float*)d_in[1];
    const float* tn     = (const float*)d_in[2];
    const float* ew     = (const float*)d_in[3];
    const float* eb     = (const float*)d_in[4];
    const float* ln1g   = (const float*)d_in[5];
    const float* ln1b   = (const float*)d_in[6];
    const float* sw     = (const float*)d_in[7];
    const float* sb     = (const float*)d_in[8];
    const float* qkvw   = (const float*)d_in[9];
    const float* qkvb   = (const float*)d_in[10];
    const float* outw   = (const float*)d_in[11];
    const float* outb   = (const float*)d_in[12];
    const float* ln2g   = (const float*)d_in[13];
    const float* ln2b   = (const float*)d_in[14];
    const float* f1w    = (const float*)d_in[15];
    const float* f1b    = (const float*)d_in[16];
    const float* f2w    = (const float*)d_in[17];
    const float* f2b    = (const float*)d_in[18];
    const float* pw     = (const float*)d_in[19];
    const float* pb     = (const float*)d_in[20];

    embed_kernel<<<B * N, 256>>>(feat, coords, tn, ew, eb);

    for (int l = 0; l < L; l++) {
        zero_zw_kernel<<<(B * M * W + 255) / 256, 256>>>();
        slice_kernel<<<B * (N / TOK1), 256>>>(ln1g, ln1b, sw, sb, l);
        qkv_kernel<<<B * M, 256>>>(qkvw, qkvb, l);
        attn_kernel<<<B * H, 256>>>();
        zp_kernel<<<B * M, 256>>>(outw, outb, l);
        ffn_kernel<<<B * (N / TOK3), 256>>>(ln2g, ln2b, f1w, f1b, f2w, f2b, l);
    }

    proj_kernel<<<(B * N) / 16, 256>>>(pw, pb, (float*)d_out);
}

// round 2
// speedup vs baseline: 1.0025x; 1.0025x over previous
#include <cuda_runtime.h>
#include <cuda_bf16.h>
#include <math.h>

// ---------------- problem constants ----------------
#define B    4
#define N    16384
#define CIN  4
#define SD   3
#define W    256
#define L    8
#define M    32
#define H    8
#define FF   1024
#define TF   4
#define DH   32          // W/H

#define TOK1 32          // tokens per block in slice kernel
#define TOK3 16          // tokens per block in ffn kernel
#define JC   128         // FF chunk in ffn kernel

// ---------------- device scratch (no allocation allowed) ----------------
__device__ float g_x[(size_t)B * N * W];        // 64 MB activations
__device__ float g_w[(size_t)B * N * M];        // 8 MB slice weights
__device__ float g_z[B * M * W];                // slice tokens (pre-norm)
__device__ float g_wsum[B * M];
__device__ float g_qkv[B * M * 3 * W];
__device__ float g_o[B * M * W];
__device__ float g_zp[B * M * W];

// ---------------- K0: time-embed + input concat + embed GEMM ----------------
__global__ void __launch_bounds__(256) embed_kernel(
    const float* __restrict__ feat, const float* __restrict__ coords,
    const float* __restrict__ tn, const float* __restrict__ ew,
    const float* __restrict__ eb)
{
    int token = blockIdx.x;          // 0 .. B*N-1
    int b = token / N;
    int c = threadIdx.x;
    __shared__ float f[16];
    if (threadIdx.x < CIN) {
        f[threadIdx.x] = feat[(size_t)token * CIN + threadIdx.x];
    } else if (threadIdx.x < CIN + SD) {
        f[threadIdx.x] = coords[(size_t)token * SD + (threadIdx.x - CIN)];
    } else if (threadIdx.x < CIN + SD + 2 * TF) {
        int k = threadIdx.x - (CIN + SD);      // 0..7
        int i = k & 3;
        float omega = powf(1000.0f, -(float)i / (float)TF);
        float ang = omega * (tn[b] * 1000.0f);
        f[threadIdx.x] = (k < TF) ? sinf(ang) : cosf(ang);
    }
    __syncthreads();
    float acc = eb[c];
#pragma unroll
    for (int k = 0; k < CIN + SD + 2 * TF; k++) acc += f[k] * ew[k * W + c];
    g_x[(size_t)token * W + c] = acc;
}

// ---------------- zero z / wsum each layer ----------------
__global__ void zero_zw_kernel()
{
    int i = blockIdx.x * 256 + threadIdx.x;
    if (i < B * M * W) g_z[i] = 0.0f;
    if (i < B * M)     g_wsum[i] = 0.0f;
}

// ---------------- K1: LN1 + slice logits + softmax + z/wsum accumulation ----
__global__ void __launch_bounds__(256) slice_kernel(
    const float* __restrict__ ln_g, const float* __restrict__ ln_b,
    const float* __restrict__ sw, const float* __restrict__ sb, int layer)
{
    __shared__ float hs[TOK1][W];       // 32 KB   LN output
    __shared__ float ws[TOK1][M];       // 4 KB    slice weights
    __shared__ float inv[TOK1];

    int nb = N / TOK1;
    int b = blockIdx.x / nb;
    int t0 = (blockIdx.x % nb) * TOK1;
    int tid = threadIdx.x;
    int warp = tid >> 5, lane = tid & 31;

    const float* g  = ln_g + layer * W;
    const float* be = ln_b + layer * W;

    // LayerNorm: 8 warps, 4 tokens each
    for (int t = warp; t < TOK1; t += 8) {
        const float* xr = g_x + ((size_t)(b * N + t0 + t)) * W;
        float v[8]; float s = 0.f, s2 = 0.f;
#pragma unroll
        for (int i = 0; i < 8; i++) { v[i] = xr[lane + 32 * i]; s += v[i]; s2 += v[i] * v[i]; }
#pragma unroll
        for (int o = 16; o > 0; o >>= 1) {
            s  += __shfl_xor_sync(0xffffffffu, s,  o);
            s2 += __shfl_xor_sync(0xffffffffu, s2, o);
        }
        float mean = s * (1.0f / W);
        float var  = s2 * (1.0f / W) - mean * mean;
        float r = rsqrtf(var + 1e-5f);
#pragma unroll
        for (int i = 0; i < 8; i++) {
            int c = lane + 32 * i;
            hs[t][c] = (v[i] - mean) * r * g[c] + be[c];
        }
    }
    __syncthreads();

    // slice logits: 32 tok x 32 m, 4 per thread
    const float* swl = sw + (size_t)layer * W * M;
    float lg[4];
#pragma unroll
    for (int r = 0; r < 4; r++) {
        int idx = tid + 256 * r;
        int t = idx / M, m = idx % M;
        float acc = sb[layer * M + m];
#pragma unroll 8
        for (int c = 0; c < W; c++) acc += hs[t][c] * swl[c * M + m];
        lg[r] = acc;
    }
#pragma unroll
    for (int r = 0; r < 4; r++) {
        int idx = tid + 256 * r;
        ws[idx / M][idx % M] = lg[r];
    }
    __syncthreads();

    // softmax over M per token
    if (tid < TOK1) {
        int t = tid;
        float mx = -1e30f;
#pragma unroll
        for (int m = 0; m < M; m++) mx = fmaxf(mx, ws[t][m]);
        float sum = 0.f;
#pragma unroll
        for (int m = 0; m < M; m++) { float e = expf(ws[t][m] - mx); ws[t][m] = e; sum += e; }
        inv[t] = 1.0f / sum;
    }
    __syncthreads();

    // normalize + write w to global
#pragma unroll
    for (int r = 0; r < 4; r++) {
        int idx = tid + 256 * r;
        int t = idx / M, m = idx % M;
        float v = ws[t][m] * inv[t];
        ws[t][m] = v;
        g_w[((size_t)(b * N + t0 + t)) * M + m] = v;
    }
    __syncthreads();

    // wsum partials
    if (tid < M) {
        float s = 0.f;
#pragma unroll
        for (int t = 0; t < TOK1; t++) s += ws[t][tid];
        atomicAdd(&g_wsum[b * M + tid], s);
    }

    // z accumulation: thread owns channel c = tid
    int c = tid;
    float zacc[M];
#pragma unroll
    for (int m = 0; m < M; m++) zacc[m] = 0.f;
    for (int t = 0; t < TOK1; t++) {
        float hv = hs[t][c];
#pragma unroll
        for (int m = 0; m < M; m++) zacc[m] += ws[t][m] * hv;
    }
#pragma unroll
    for (int m = 0; m < M; m++) atomicAdd(&g_z[(b * M + m) * W + c], zacc[m]);
}

// ---------------- K2a: z/wsum -> qkv ----------------
__global__ void __launch_bounds__(256) qkv_kernel(
    const float* __restrict__ qkvw, const float* __restrict__ qkvb, int layer)
{
    int b = blockIdx.x / M, m = blockIdx.x % M;
    __shared__ float zs[W];
    float wsv = fmaxf(g_wsum[b * M + m], 1e-8f);
    zs[threadIdx.x] = g_z[(b * M + m) * W + threadIdx.x] / wsv;
    __syncthreads();
    const float* wq = qkvw + (size_t)layer * W * 3 * W;
#pragma unroll
    for (int r = 0; r < 3; r++) {
        int j = threadIdx.x + 256 * r;
        float acc = qkvb[layer * 3 * W + j];
#pragma unroll 8
        for (int c = 0; c < W; c++) acc += zs[c] * wq[(size_t)c * (3 * W) + j];
        g_qkv[(size_t)(b * M + m) * (3 * W) + j] = acc;
    }
}

// ---------------- K2b: 32x32 latent attention per (b,h) ----------------
__global__ void __launch_bounds__(256) attn_kernel()
{
    int b = blockIdx.x / H, h = blockIdx.x % H;
    __shared__ float q[M][DH], k[M][DH], v[M][DH], a[M][M];
    int tid = threadIdx.x;
    for (int i = tid; i < M * DH; i += 256) {
        int m = i / DH, d = i % DH;
        const float* base = g_qkv + (size_t)(b * M + m) * (3 * W);
        q[m][d] = base[h * DH + d];
        k[m][d] = base[W + h * DH + d];
        v[m][d] = base[2 * W + h * DH + d];
    }
    __syncthreads();
    const float scale = 0.17677669529663687f;   // 1/sqrt(32)
    for (int i = tid; i < M * M; i += 256) {
        int m = i / M, n2 = i % M;
        float acc = 0.f;
#pragma unroll
        for (int d = 0; d < DH; d++) acc += q[m][d] * k[n2][d];
        a[m][n2] = acc * scale;
    }
    __syncthreads();
    if (tid < M) {
        float mx = -1e30f;
#pragma unroll
        for (int n2 = 0; n2 < M; n2++) mx = fmaxf(mx, a[tid][n2]);
        float s = 0.f;
#pragma unroll
        for (int n2 = 0; n2 < M; n2++) { float e = expf(a[tid][n2] - mx); a[tid][n2] = e; s += e; }
        float is = 1.0f / s;
#pragma unroll
        for (int n2 = 0; n2 < M; n2++) a[tid][n2] *= is;
    }
    __syncthreads();
    for (int i = tid; i < M * DH; i += 256) {
        int m = i / DH, d = i % DH;
        float acc = 0.f;
#pragma unroll
        for (int n2 = 0; n2 < M; n2++) acc += a[m][n2] * v[n2][d];
        g_o[(size_t)(b * M + m) * W + h * DH + d] = acc;
    }
}

// ---------------- K2c: zp = o @ out_w + out_b ----------------
__global__ void __launch_bounds__(256) zp_kernel(
    const float* __restrict__ ow, const float* __restrict__ ob, int layer)
{
    int b = blockIdx.x / M, m = blockIdx.x % M;
    __shared__ float os[W];
    os[threadIdx.x] = g_o[(size_t)(b * M + m) * W + threadIdx.x];
    __syncthreads();
    const float* wl = ow + (size_t)layer * W * W;
    int c = threadIdx.x;
    float acc = ob[layer * W + c];
#pragma unroll 8
    for (int k2 = 0; k2 < W; k2++) acc += os[k2] * wl[(size_t)k2 * W + c];
    g_zp[(size_t)(b * M + m) * W + c] = acc;
}

// ---------------- K3: broadcast-back + residual + LN2 + FFN + residual -----
__global__ void __launch_bounds__(256) ffn_kernel(
    const float* __restrict__ ln2g, const float* __restrict__ ln2b,
    const float* __restrict__ f1w, const float* __restrict__ f1b,
    const float* __restrict__ f2w, const float* __restrict__ f2b, int layer)
{
    __shared__ float xh[TOK3][W];    // 16 KB  x_mid then h2 (in-place)
    __shared__ float ts[TOK3][JC];   // 8 KB   gelu(ffn1) chunk
    __shared__ float wt[TOK3][M];    // 2 KB   slice weights tile

    int nb = N / TOK3;
    int b = blockIdx.x / nb;
    int t0 = (blockIdx.x % nb) * TOK3;
    int tid = threadIdx.x;

    // zp column (this thread's channel) in registers
    float zpc[M];
#pragma unroll
    for (int m = 0; m < M; m++) zpc[m] = g_zp[(size_t)(b * M + m) * W + tid];

    for (int i = tid; i < TOK3 * M; i += 256)
        wt[i / M][i % M] = g_w[((size_t)(b * N) + t0 + i / M) * M + (i % M)];
    __syncthreads();

    // x_mid = x + w @ zp ; outacc starts the second residual (+ffn2_b)
    const float* f2bl = f2b + layer * W;
    float outacc[TOK3];
    float bias2 = f2bl[tid];
#pragma unroll
    for (int t = 0; t < TOK3; t++) {
        float acc = g_x[((size_t)(b * N) + t0 + t) * W + tid];
#pragma unroll
        for (int m = 0; m < M; m++) acc += wt[t][m] * zpc[m];
        xh[t][tid] = acc;
        outacc[t] = acc + bias2;
    }
    __syncthreads();

    // LayerNorm2 in place: 8 warps x 2 tokens
    int warp = tid >> 5, lane = tid & 31;
    const float* g2 = ln2g + layer * W;
    const float* b2 = ln2b + layer * W;
    for (int t = warp; t < TOK3; t += 8) {
        float v[8]; float s = 0.f, s2 = 0.f;
#pragma unroll
        for (int i = 0; i < 8; i++) { v[i] = xh[t][lane + 32 * i]; s += v[i]; s2 += v[i] * v[i]; }
#pragma unroll
        for (int o = 16; o > 0; o >>= 1) {
            s  += __shfl_xor_sync(0xffffffffu, s,  o);
            s2 += __shfl_xor_sync(0xffffffffu, s2, o);
        }
        float mean = s * (1.0f / W);
        float var  = s2 * (1.0f / W) - mean * mean;
        float r = rsqrtf(var + 1e-5f);
#pragma unroll
        for (int i = 0; i < 8; i++) {
            int c = lane + 32 * i;
            xh[t][c] = (v[i] - mean) * r * g2[c] + b2[c];
        }
    }
    __syncthreads();

    const float* w1 = f1w + (size_t)layer * W * FF;
    const float* w2 = f2w + (size_t)layer * FF * W;
    const float* b1 = f1b + layer * FF;
    int jloc = tid & (JC - 1);
    int tg   = tid >> 7;     // token group 0/1 (8 tokens each)

    for (int jc = 0; jc < FF; jc += JC) {
        int j = jc + jloc;
        float acc8[8];
        float bj = b1[j];
#pragma unroll
        for (int i = 0; i < 8; i++) acc8[i] = bj;
        for (int c = 0; c < W; c++) {
            float wv = w1[(size_t)c * FF + j];
#pragma unroll
            for (int i = 0; i < 8; i++) acc8[i] += xh[tg * 8 + i][c] * wv;
        }
#pragma unroll
        for (int i = 0; i < 8; i++) {
            float xg = acc8[i];
            ts[tg * 8 + i][jloc] = 0.5f * xg * (1.0f + erff(xg * 0.7071067811865476f));
        }
        __syncthreads();
        for (int jj = 0; jj < JC; jj++) {
            float wv = w2[(size_t)(jc + jj) * W + tid];
#pragma unroll
            for (int t = 0; t < TOK3; t++) outacc[t] += ts[t][jj] * wv;
        }
        __syncthreads();
    }

#pragma unroll
    for (int t = 0; t < TOK3; t++)
        g_x[((size_t)(b * N) + t0 + t) * W + tid] = outacc[t];
}

// ---------------- K5: final projection ----------------
__global__ void __launch_bounds__(256) proj_kernel(
    const float* __restrict__ pw, const float* __restrict__ pb,
    float* __restrict__ out)
{
    __shared__ float xs[16][W];
    size_t t0 = (size_t)blockIdx.x * 16;
    for (int i = threadIdx.x; i < 16 * W; i += 256)
        xs[i >> 8][i & 255] = g_x[t0 * W + i];
    __syncthreads();
    if (threadIdx.x < 64) {
        int t = threadIdx.x >> 2, o = threadIdx.x & 3;
        float acc = pb[o];
#pragma unroll 8
        for (int c = 0; c < W; c++) acc += xs[t][c] * pw[c * CIN + o];
        out[(t0 + t) * CIN + o] = acc;
    }
}

// ---------------- launch ----------------
extern "C" void kernel_launch(void* const* d_in, const int* in_sizes, int n_in,
                              void* d_out, int out_size)
{
    const float* feat   = (const float*)d_in[0];
    const float* coords = (const float*)d_in[1];
    const float* tn     = (const float*)d_in[2];
    const float* ew     = (const float*)d_in[3];
    const float* eb     = (const float*)d_in[4];
    const float* ln1g   = (const float*)d_in[5];
    const float* ln1b   = (const float*)d_in[6];
    const float* sw     = (const float*)d_in[7];
    const float* sb     = (const float*)d_in[8];
    const float* qkvw   = (const float*)d_in[9];
    const float* qkvb   = (const float*)d_in[10];
    const float* outw   = (const float*)d_in[11];
    const float* outb   = (const float*)d_in[12];
    const float* ln2g   = (const float*)d_in[13];
    const float* ln2b   = (const float*)d_in[14];
    const float* f1w    = (const float*)d_in[15];
    const float* f1b    = (const float*)d_in[16];
    const float* f2w    = (const float*)d_in[17];
    const float* f2b    = (const float*)d_in[18];
    const float* pw     = (const float*)d_in[19];
    const float* pb     = (const float*)d_in[20];

    embed_kernel<<<B * N, 256>>>(feat, coords, tn, ew, eb);

    for (int l = 0; l < L; l++) {
        zero_zw_kernel<<<(B * M * W + 255) / 256, 256>>>();
        slice_kernel<<<B * (N / TOK1), 256>>>(ln1g, ln1b, sw, sb, l);
        qkv_kernel<<<B * M, 256>>>(qkvw, qkvb, l);
        attn_kernel<<<B * H, 256>>>();
        zp_kernel<<<B * M, 256>>>(outw, outb, l);
        ffn_kernel<<<B * (N / TOK3), 256>>>(ln2g, ln2b, f1w, f1b, f2w, f2b, l);
    }

    proj_kernel<<<(B * N) / 16, 256>>>(pw, pb, (float*)d_out);
}

// round 5
// speedup vs baseline: 2.7209x; 2.7141x over previous
#include <cuda_runtime.h>
#include <math.h>
#include <stdint.h>

#define B    4
#define N    16384
#define CIN  4
#define SD   3
#define W    256
#define L    8
#define M    32
#define H    8
#define FF   1024
#define TF   4
#define DH   32
#define TOK1 32
#define TOKF 128

__device__ float g_x[(size_t)B * N * W];
__device__ float g_w[(size_t)B * N * M];
__device__ float g_z[B * M * W];
__device__ float g_wsum[B * M];
__device__ float g_qkv[B * M * 3 * W];
__device__ float g_o[B * M * W];
__device__ float g_zp[B * M * W];
__device__ float g_w1t[(size_t)L * FF * W];   // [L][FF][Wperm] tf32, k-pair permuted
__device__ float g_w2t[(size_t)L * W * FF];   // [L][W][FFperm] tf32, k-pair permuted

// ---------- helpers ----------
__device__ __forceinline__ float to_tf32(float x) {
    uint32_t r; asm("cvt.rna.tf32.f32 %0, %1;" : "=r"(r) : "f"(x));
    return __uint_as_float(r);
}
// within each 8-k group store order (0,4,1,5,2,6,3,7) so (k, k+4) are adjacent
__device__ __forceinline__ int kperm(int k) {
    return (k & ~7) | ((k & 3) << 1) | ((k >> 2) & 1);
}
// swizzled smem word offset for row-major [R][S] with permuted k and 8-word-block XOR by row
__device__ __forceinline__ int swz(int r, int k, int S) {
    return r * S + ((((k >> 3) ^ (r & 7)) << 3) | ((k & 3) << 1) | ((k >> 2) & 1));
}
__device__ __forceinline__ void mma8(float* d, const uint32_t* a, const uint32_t* b) {
    asm volatile("mma.sync.aligned.m16n8k8.row.col.f32.tf32.tf32.f32 "
        "{%0,%1,%2,%3}, {%4,%5,%6,%7}, {%8,%9}, {%0,%1,%2,%3};"
        : "+f"(d[0]), "+f"(d[1]), "+f"(d[2]), "+f"(d[3])
        : "r"(a[0]), "r"(a[1]), "r"(a[2]), "r"(a[3]), "r"(b[0]), "r"(b[1]));
}

// ---------------- K0: embed ----------------
__global__ void __launch_bounds__(256) embed_kernel(
    const float* __restrict__ feat, const float* __restrict__ coords,
    const float* __restrict__ tn, const float* __restrict__ ew, const float* __restrict__ eb)
{
    int token = blockIdx.x, b = token / N, c = threadIdx.x;
    __shared__ float f[16];
    if (threadIdx.x < CIN) f[threadIdx.x] = feat[(size_t)token * CIN + threadIdx.x];
    else if (threadIdx.x < CIN + SD) f[threadIdx.x] = coords[(size_t)token * SD + (threadIdx.x - CIN)];
    else if (threadIdx.x < CIN + SD + 2 * TF) {
        int k = threadIdx.x - (CIN + SD), i = k & 3;
        float ang = powf(1000.0f, -(float)i / (float)TF) * (tn[b] * 1000.0f);
        f[threadIdx.x] = (k < TF) ? sinf(ang) : cosf(ang);
    }
    __syncthreads();
    float acc = eb[c];
#pragma unroll
    for (int k = 0; k < CIN + SD + 2 * TF; k++) acc += f[k] * ew[k * W + c];
    g_x[(size_t)token * W + c] = acc;
}

// ---------------- weight transform (tf32 + transpose + k-pair permute) ------
__global__ void __launch_bounds__(256) w1t_kernel(const float* __restrict__ f1w)
{
    int idx = blockIdx.x * 256 + threadIdx.x;            // L*FF*W
    int l = idx / (FF * W), r = idx % (FF * W), j = r / W, c = r % W;
    g_w1t[((size_t)l * FF + j) * W + kperm(c)] =
        to_tf32(f1w[((size_t)l * W + c) * FF + j]);
}
__global__ void __launch_bounds__(256) w2t_kernel(const float* __restrict__ f2w)
{
    int idx = blockIdx.x * 256 + threadIdx.x;            // L*W*FF
    int l = idx / (W * FF), r = idx % (W * FF), c = r / FF, j = r % FF;
    g_w2t[((size_t)l * W + c) * FF + kperm(j)] =
        to_tf32(f2w[((size_t)l * FF + j) * W + c]);
}

__global__ void zero_zw_kernel()
{
    int i = blockIdx.x * 256 + threadIdx.x;
    if (i < B * M * W) g_z[i] = 0.0f;
    if (i < B * M) g_wsum[i] = 0.0f;
}

// ---------------- K1: slice ----------------
__global__ void __launch_bounds__(256) slice_kernel(
    const float* __restrict__ ln_g, const float* __restrict__ ln_b,
    const float* __restrict__ sw, const float* __restrict__ sb, int layer)
{
    __shared__ float hs[TOK1][W];
    __shared__ float ws[TOK1][M];
    __shared__ float inv[TOK1];
    int nb = N / TOK1, b = blockIdx.x / nb, t0 = (blockIdx.x % nb) * TOK1;
    int tid = threadIdx.x, warp = tid >> 5, lane = tid & 31;
    const float* g = ln_g + layer * W;
    const float* be = ln_b + layer * W;

    for (int t = warp; t < TOK1; t += 8) {
        const float* xr = g_x + ((size_t)(b * N + t0 + t)) * W;
        float v[8]; float s = 0.f, s2 = 0.f;
#pragma unroll
        for (int i = 0; i < 8; i++) { v[i] = xr[lane + 32 * i]; s += v[i]; s2 += v[i] * v[i]; }
#pragma unroll
        for (int o = 16; o > 0; o >>= 1) {
            s += __shfl_xor_sync(0xffffffffu, s, o);
            s2 += __shfl_xor_sync(0xffffffffu, s2, o);
        }
        float mean = s * (1.0f / W), var = s2 * (1.0f / W) - mean * mean;
        float r = rsqrtf(var + 1e-5f);
#pragma unroll
        for (int i = 0; i < 8; i++) {
            int c = lane + 32 * i;
            hs[t][c] = (v[i] - mean) * r * g[c] + be[c];
        }
    }
    __syncthreads();
    const float* swl = sw + (size_t)layer * W * M;
    float lg[4];
#pragma unroll
    for (int r = 0; r < 4; r++) {
        int idx = tid + 256 * r, t = idx / M, m = idx % M;
        float acc = sb[layer * M + m];
#pragma unroll 8
        for (int c = 0; c < W; c++) acc += hs[t][c] * swl[c * M + m];
        lg[r] = acc;
    }
#pragma unroll
    for (int r = 0; r < 4; r++) { int idx = tid + 256 * r; ws[idx / M][idx % M] = lg[r]; }
    __syncthreads();
    if (tid < TOK1) {
        float mx = -1e30f;
#pragma unroll
        for (int m = 0; m < M; m++) mx = fmaxf(mx, ws[tid][m]);
        float sum = 0.f;
#pragma unroll
        for (int m = 0; m < M; m++) { float e = expf(ws[tid][m] - mx); ws[tid][m] = e; sum += e; }
        inv[tid] = 1.0f / sum;
    }
    __syncthreads();
#pragma unroll
    for (int r = 0; r < 4; r++) {
        int idx = tid + 256 * r, t = idx / M, m = idx % M;
        float v = ws[t][m] * inv[t];
        ws[t][m] = v;
        g_w[((size_t)(b * N + t0 + t)) * M + m] = v;
    }
    __syncthreads();
    if (tid < M) {
        float s = 0.f;
#pragma unroll
        for (int t = 0; t < TOK1; t++) s += ws[t][tid];
        atomicAdd(&g_wsum[b * M + tid], s);
    }
    float zacc[M];
#pragma unroll
    for (int m = 0; m < M; m++) zacc[m] = 0.f;
    for (int t = 0; t < TOK1; t++) {
        float hv = hs[t][tid];
#pragma unroll
        for (int m = 0; m < M; m++) zacc[m] += ws[t][m] * hv;
    }
#pragma unroll
    for (int m = 0; m < M; m++) atomicAdd(&g_z[(b * M + m) * W + tid], zacc[m]);
}

// ---------------- K2a/b/c ----------------
__global__ void __launch_bounds__(256) qkv_kernel(
    const float* __restrict__ qkvw, const float* __restrict__ qkvb, int layer)
{
    int b = blockIdx.x / M, m = blockIdx.x % M;
    __shared__ float zs[W];
    float wsv = fmaxf(g_wsum[b * M + m], 1e-8f);
    zs[threadIdx.x] = g_z[(b * M + m) * W + threadIdx.x] / wsv;
    __syncthreads();
    const float* wq = qkvw + (size_t)layer * W * 3 * W;
#pragma unroll
    for (int r = 0; r < 3; r++) {
        int j = threadIdx.x + 256 * r;
        float acc = qkvb[layer * 3 * W + j];
#pragma unroll 8
        for (int c = 0; c < W; c++) acc += zs[c] * wq[(size_t)c * (3 * W) + j];
        g_qkv[(size_t)(b * M + m) * (3 * W) + j] = acc;
    }
}
__global__ void __launch_bounds__(256) attn_kernel()
{
    int b = blockIdx.x / H, h = blockIdx.x % H;
    __shared__ float q[M][DH], k[M][DH], v[M][DH], a[M][M];
    int tid = threadIdx.x;
    for (int i = tid; i < M * DH; i += 256) {
        int m = i / DH, d = i % DH;
        const float* base = g_qkv + (size_t)(b * M + m) * (3 * W);
        q[m][d] = base[h * DH + d];
        k[m][d] = base[W + h * DH + d];
        v[m][d] = base[2 * W + h * DH + d];
    }
    __syncthreads();
    const float scale = 0.17677669529663687f;
    for (int i = tid; i < M * M; i += 256) {
        int m = i / M, n2 = i % M;
        float acc = 0.f;
#pragma unroll
        for (int d = 0; d < DH; d++) acc += q[m][d] * k[n2][d];
        a[m][n2] = acc * scale;
    }
    __syncthreads();
    if (tid < M) {
        float mx = -1e30f;
#pragma unroll
        for (int n2 = 0; n2 < M; n2++) mx = fmaxf(mx, a[tid][n2]);
        float s = 0.f;
#pragma unroll
        for (int n2 = 0; n2 < M; n2++) { float e = expf(a[tid][n2] - mx); a[tid][n2] = e; s += e; }
        float is = 1.0f / s;
#pragma unroll
        for (int n2 = 0; n2 < M; n2++) a[tid][n2] *= is;
    }
    __syncthreads();
    for (int i = tid; i < M * DH; i += 256) {
        int m = i / DH, d = i % DH;
        float acc = 0.f;
#pragma unroll
        for (int n2 = 0; n2 < M; n2++) acc += a[m][n2] * v[n2][d];
        g_o[(size_t)(b * M + m) * W + h * DH + d] = acc;
    }
}
__global__ void __launch_bounds__(256) zp_kernel(
    const float* __restrict__ ow, const float* __restrict__ ob, int layer)
{
    int b = blockIdx.x / M, m = blockIdx.x % M;
    __shared__ float os[W];
    os[threadIdx.x] = g_o[(size_t)(b * M + m) * W + threadIdx.x];
    __syncthreads();
    const float* wl = ow + (size_t)layer * W * W;
    float acc = ob[layer * W + threadIdx.x];
#pragma unroll 8
    for (int k2 = 0; k2 < W; k2++) acc += os[k2] * wl[(size_t)k2 * W + threadIdx.x];
    g_zp[(size_t)(b * M + m) * W + threadIdx.x] = acc;
}

// ---------------- K3: FFN with mma.sync tf32 ----------------
// smem: h2 [128][256] swizzled (131072 B) + G [128][128] swizzled (65536 B)
#define SMW_G  32768
#define SM_FFN_BYTES 196608

__global__ void __launch_bounds__(512, 1) ffn_mma_kernel(
    const float* __restrict__ ln2g, const float* __restrict__ ln2b,
    const float* __restrict__ f1b, const float* __restrict__ f2b, int layer)
{
    extern __shared__ float sm[];
    float* s_h2 = sm;
    float* s_g  = sm + SMW_G;
    int tid = threadIdx.x;
    int warp = tid >> 5, lane = tid & 31, g = lane >> 2, tig = lane & 3;
    int nb = N / TOKF, b = blockIdx.x / nb, t0 = (blockIdx.x % nb) * TOKF;
    size_t xbase = ((size_t)(b * N) + t0) * W;

    // ---- prologue: x_mid = x + w@zp ----
    int c = tid & 255, half = tid >> 8;
    float zpc[M];
#pragma unroll
    for (int m = 0; m < M; m++) zpc[m] = g_zp[(size_t)(b * M + m) * W + c];
    for (int i = tid; i < TOKF * M; i += 512)
        s_g[i] = g_w[((size_t)(b * N) + t0 + i / M) * M + (i % M)];
    __syncthreads();
    for (int t = half * 64; t < half * 64 + 64; t++) {
        float acc = g_x[xbase + (size_t)t * W + c];
#pragma unroll
        for (int m = 0; m < M; m++) acc += s_g[t * M + m] * zpc[m];
        g_x[xbase + (size_t)t * W + c] = acc;     // keep x_mid for residual
        s_h2[swz(t, c, 256)] = acc;
    }
    __syncthreads();

    // ---- LN2 in place (tf32-rounded) ----
    {
        const float* g2 = ln2g + layer * W;
        const float* b2 = ln2b + layer * W;
        for (int rr = 0; rr < 8; rr++) {
            int r = warp * 8 + rr;
            float v[8]; float s = 0.f, s2 = 0.f;
#pragma unroll
            for (int i = 0; i < 8; i++) {
                v[i] = s_h2[swz(r, lane + 32 * i, 256)];
                s += v[i]; s2 += v[i] * v[i];
            }
#pragma unroll
            for (int o = 16; o > 0; o >>= 1) {
                s += __shfl_xor_sync(0xffffffffu, s, o);
                s2 += __shfl_xor_sync(0xffffffffu, s2, o);
            }
            float mean = s * (1.0f / W), var = s2 * (1.0f / W) - mean * mean;
            float rs = rsqrtf(var + 1e-5f);
#pragma unroll
            for (int i = 0; i < 8; i++) {
                int cc = lane + 32 * i;
                s_h2[swz(r, cc, 256)] = to_tf32((v[i] - mean) * rs * g2[cc] + b2[cc]);
            }
        }
    }
    __syncthreads();

    const float* w1l = g_w1t + (size_t)layer * FF * W;
    const float* w2l = g_w2t + (size_t)layer * W * FF;
    const float* b1l = f1b + layer * FF;

    int wm = warp >> 2, wn = warp & 3;       // 4x4 warp grid
    float d2[2][8][4];
#pragma unroll
    for (int mt = 0; mt < 2; mt++)
#pragma unroll
        for (int nt = 0; nt < 8; nt++)
#pragma unroll
            for (int q = 0; q < 4; q++) d2[mt][nt][q] = 0.f;

    for (int chunk = 0; chunk < 8; chunk++) {
        int j0 = chunk * 128;

        // ===== GEMM1: D1[128x128] = h2 @ W1T(j-chunk), K=256 =====
        float d1[2][4][4];
#pragma unroll
        for (int mt = 0; mt < 2; mt++)
#pragma unroll
            for (int nt = 0; nt < 4; nt++)
#pragma unroll
                for (int q = 0; q < 4; q++) d1[mt][nt][q] = 0.f;

#pragma unroll 4
        for (int ks = 0; ks < 32; ks++) {
            int kx = ((ks ^ g) << 3) + 2 * tig;
            uint32_t af[2][4];
#pragma unroll
            for (int mt = 0; mt < 2; mt++) {
                int r0 = wm * 32 + mt * 16 + g;
                float2 v0 = *(const float2*)&s_h2[r0 * 256 + kx];
                float2 v1 = *(const float2*)&s_h2[(r0 + 8) * 256 + kx];
                af[mt][0] = __float_as_uint(v0.x);
                af[mt][1] = __float_as_uint(v1.x);
                af[mt][2] = __float_as_uint(v0.y);
                af[mt][3] = __float_as_uint(v1.y);
            }
#pragma unroll
            for (int nt = 0; nt < 4; nt++) {
                int j = j0 + wn * 32 + nt * 8 + g;
                float2 bv = *(const float2*)&w1l[(size_t)j * W + ks * 8 + 2 * tig];
                uint32_t bf[2] = { __float_as_uint(bv.x), __float_as_uint(bv.y) };
                mma8(d1[0][nt], af[0], bf);
                mma8(d1[1][nt], af[1], bf);
            }
        }
        __syncthreads();   // prior chunk's GEMM2 reads of s_g complete

        // ===== bias + gelu -> G (tf32) =====
#pragma unroll
        for (int mt = 0; mt < 2; mt++) {
#pragma unroll
            for (int nt = 0; nt < 4; nt++) {
                int row = wm * 32 + mt * 16 + g;
                int jc = wn * 32 + nt * 8 + 2 * tig;
#pragma unroll
                for (int q = 0; q < 4; q++) {
                    int rr = row + (q >> 1) * 8;
                    int jj = jc + (q & 1);
                    float x = d1[mt][nt][q] + b1l[j0 + jj];
                    float gl = 0.5f * x * (1.0f + erff(x * 0.7071067811865476f));
                    s_g[swz(rr, jj, 128)] = to_tf32(gl);
                }
            }
        }
        __syncthreads();

        // ===== GEMM2 partial: D2[128x256] += G @ W2T(chunk), K=128 =====
#pragma unroll 2
        for (int ks = 0; ks < 16; ks++) {
            int kx = ((ks ^ g) << 3) + 2 * tig;
            uint32_t af[2][4];
#pragma unroll
            for (int mt = 0; mt < 2; mt++) {
                int r0 = wm * 32 + mt * 16 + g;
                float2 v0 = *(const float2*)&s_g[r0 * 128 + kx];
                float2 v1 = *(const float2*)&s_g[(r0 + 8) * 128 + kx];
                af[mt][0] = __float_as_uint(v0.x);
                af[mt][1] = __float_as_uint(v1.x);
                af[mt][2] = __float_as_uint(v0.y);
                af[mt][3] = __float_as_uint(v1.y);
            }
#pragma unroll
            for (int nt = 0; nt < 8; nt++) {
                int cc = wn * 64 + nt * 8 + g;
                float2 bv = *(const float2*)&w2l[(size_t)cc * FF + j0 + ks * 8 + 2 * tig];
                uint32_t bf[2] = { __float_as_uint(bv.x), __float_as_uint(bv.y) };
                mma8(d2[0][nt], af[0], bf);
                mma8(d2[1][nt], af[1], bf);
            }
        }
    }

    // ---- epilogue: x = x_mid + D2 + b2 ----
    const float* b2l = f2b + layer * W;
#pragma unroll
    for (int mt = 0; mt < 2; mt++) {
#pragma unroll
        for (int nt = 0; nt < 8; nt++) {
            int col = wn * 64 + nt * 8 + 2 * tig;
            int ra = wm * 32 + mt * 16 + g;
            float2 xm = *(const float2*)&g_x[xbase + (size_t)ra * W + col];
            float2 o;
            o.x = xm.x + d2[mt][nt][0] + b2l[col];
            o.y = xm.y + d2[mt][nt][1] + b2l[col + 1];
            *(float2*)&g_x[xbase + (size_t)ra * W + col] = o;
            int rb = ra + 8;
            float2 xm2 = *(const float2*)&g_x[xbase + (size_t)rb * W + col];
            o.x = xm2.x + d2[mt][nt][2] + b2l[col];
            o.y = xm2.y + d2[mt][nt][3] + b2l[col + 1];
            *(float2*)&g_x[xbase + (size_t)rb * W + col] = o;
        }
    }
}

// ---------------- K5: final projection ----------------
__global__ void __launch_bounds__(256) proj_kernel(
    const float* __restrict__ pw, const float* __restrict__ pb, float* __restrict__ out)
{
    __shared__ float xs[16][W];
    size_t t0 = (size_t)blockIdx.x * 16;
    for (int i = threadIdx.x; i < 16 * W; i += 256)
        xs[i >> 8][i & 255] = g_x[t0 * W + i];
    __syncthreads();
    if (threadIdx.x < 64) {
        int t = threadIdx.x >> 2, o = threadIdx.x & 3;
        float acc = pb[o];
#pragma unroll 8
        for (int c = 0; c < W; c++) acc += xs[t][c] * pw[c * CIN + o];
        out[(t0 + t) * CIN + o] = acc;
    }
}

// ---------------- launch ----------------
extern "C" void kernel_launch(void* const* d_in, const int* in_sizes, int n_in,
                              void* d_out, int out_size)
{
    const float* feat = (const float*)d_in[0];
    const float* coords = (const float*)d_in[1];
    const float* tn   = (const float*)d_in[2];
    const float* ew   = (const float*)d_in[3];
    const float* eb   = (const float*)d_in[4];
    const float* ln1g = (const float*)d_in[5];
    const float* ln1b = (const float*)d_in[6];
    const float* sw   = (const float*)d_in[7];
    const float* sb   = (const float*)d_in[8];
    const float* qkvw = (const float*)d_in[9];
    const float* qkvb = (const float*)d_in[10];
    const float* outw = (const float*)d_in[11];
    const float* outb = (const float*)d_in[12];
    const float* ln2g = (const float*)d_in[13];
    const float* ln2b = (const float*)d_in[14];
    const float* f1w  = (const float*)d_in[15];
    const float* f1b  = (const float*)d_in[16];
    const float* f2w  = (const float*)d_in[17];
    const float* f2b  = (const float*)d_in[18];
    const float* pw   = (const float*)d_in[19];
    const float* pb   = (const float*)d_in[20];

    static int smem_set = 0;
    if (!smem_set) {
        cudaFuncSetAttribute(ffn_mma_kernel, cudaFuncAttributeMaxDynamicSharedMemorySize, SM_FFN_BYTES);
        smem_set = 1;
    }

    embed_kernel<<<B * N, 256>>>(feat, coords, tn, ew, eb);
    w1t_kernel<<<L * FF * W / 256, 256>>>(f1w);
    w2t_kernel<<<L * W * FF / 256, 256>>>(f2w);

    for (int l = 0; l < L; l++) {
        zero_zw_kernel<<<(B * M * W + 255) / 256, 256>>>();
        slice_kernel<<<B * (N / TOK1), 256>>>(ln1g, ln1b, sw, sb, l);
        qkv_kernel<<<B * M, 256>>>(qkvw, qkvb, l);
        attn_kernel<<<B * H, 256>>>();
        zp_kernel<<<B * M, 256>>>(outw, outb, l);
        ffn_mma_kernel<<<B * (N / TOKF), 512, SM_FFN_BYTES>>>(ln2g, ln2b, f1b, f2b, l);
    }

    proj_kernel<<<(B * N) / 16, 256>>>(pw, pb, (float*)d_out);
}